// round 5
// baseline (speedup 1.0000x reference)
#include <cuda_runtime.h>

// ---------------------------------------------------------------------------
// MHA cross-attention, fp32 baseline.
//   q = x1 @ Wq^T + bq ; k,v = x2 @ W{k,v}^T + b ; per-head flash attention
//   (scale 1/sqrt(C)); out = concat @ Wu^T + bu, output (B,T,C).
// x layout (T,B,C): row r = t*B+b is contiguous. Q/K/V staged as [B][H][T][hd].
// ---------------------------------------------------------------------------

constexpr int T_  = 2048;
constexpr int B_  = 4;
constexpr int C_  = 1024;
constexpr int H_  = 16;
constexpr int HD_ = 64;
constexpr int M_  = T_ * B_;   // 8192 rows

// Scratch (device globals: allocation-free per harness rules). 4 x 32MB.
__device__ float g_Q[B_ * H_ * T_ * HD_];
__device__ float g_K[B_ * H_ * T_ * HD_];
__device__ float g_V[B_ * H_ * T_ * HD_];
__device__ float g_AO[B_ * T_ * C_];

// ---------------------------------------------------------------------------
// SGEMM: Y = X(MxK) @ W^T(N x K) + bias.  M=8192, N=K=1024.
// 128x128 block, BK=8, 256 threads, 8x8 per thread, double-buffered smem.
// MODE 0: scatter into QKV layout [b][h][t][d]  (r = t*B+b, n = h*64+d)
// MODE 1: plain Y[r*C + n]
// ---------------------------------------------------------------------------
template <int MODE>
__global__ void __launch_bounds__(256) proj_kernel(
    const float* __restrict__ X, const float* __restrict__ W,
    const float* __restrict__ bias, float* __restrict__ Y)
{
    __shared__ float As[2][8][128];   // [buf][k][m]
    __shared__ float Bs[2][8][128];   // [buf][k][n]

    const int tid = threadIdx.x;
    const int bm  = blockIdx.y * 128;
    const int bn  = blockIdx.x * 128;
    const int lr  = tid >> 1;          // 0..127
    const int lc  = (tid & 1) * 4;     // 0 or 4
    const int tx  = tid & 15;
    const int ty  = tid >> 4;

    const float* Xp = X + (bm + lr) * C_ + lc;
    const float* Wp = W + (bn + lr) * C_ + lc;

    float acc[8][8];
#pragma unroll
    for (int i = 0; i < 8; i++)
#pragma unroll
        for (int j = 0; j < 8; j++) acc[i][j] = 0.f;

    // preload tile 0
    {
        float4 a = *(const float4*)Xp;
        float4 b = *(const float4*)Wp;
        As[0][lc + 0][lr] = a.x; As[0][lc + 1][lr] = a.y;
        As[0][lc + 2][lr] = a.z; As[0][lc + 3][lr] = a.w;
        Bs[0][lc + 0][lr] = b.x; Bs[0][lc + 1][lr] = b.y;
        Bs[0][lc + 2][lr] = b.z; Bs[0][lc + 3][lr] = b.w;
    }
    __syncthreads();

    int buf = 0;
    const int KBLK = C_ / 8;   // 128
    for (int kt = 0; kt < KBLK; kt++) {
        float4 na, nb;
        const bool has_next = (kt + 1) < KBLK;
        if (has_next) {
            na = *(const float4*)(Xp + (kt + 1) * 8);
            nb = *(const float4*)(Wp + (kt + 1) * 8);
        }
#pragma unroll
        for (int k = 0; k < 8; k++) {
            float4 a0 = *(const float4*)&As[buf][k][ty * 4];
            float4 a1 = *(const float4*)&As[buf][k][ty * 4 + 64];
            float4 b0 = *(const float4*)&Bs[buf][k][tx * 4];
            float4 b1 = *(const float4*)&Bs[buf][k][tx * 4 + 64];
            float av[8] = {a0.x, a0.y, a0.z, a0.w, a1.x, a1.y, a1.z, a1.w};
            float bv[8] = {b0.x, b0.y, b0.z, b0.w, b1.x, b1.y, b1.z, b1.w};
#pragma unroll
            for (int i = 0; i < 8; i++)
#pragma unroll
                for (int j = 0; j < 8; j++)
                    acc[i][j] = fmaf(av[i], bv[j], acc[i][j]);
        }
        if (has_next) {
            As[buf ^ 1][lc + 0][lr] = na.x; As[buf ^ 1][lc + 1][lr] = na.y;
            As[buf ^ 1][lc + 2][lr] = na.z; As[buf ^ 1][lc + 3][lr] = na.w;
            Bs[buf ^ 1][lc + 0][lr] = nb.x; Bs[buf ^ 1][lc + 1][lr] = nb.y;
            Bs[buf ^ 1][lc + 2][lr] = nb.z; Bs[buf ^ 1][lc + 3][lr] = nb.w;
            __syncthreads();
            buf ^= 1;
        }
    }

    // epilogue
#pragma unroll
    for (int i = 0; i < 8; i++) {
        const int r = bm + (i >> 2) * 64 + ty * 4 + (i & 3);
#pragma unroll
        for (int j = 0; j < 8; j++) {
            const int n = bn + (j >> 2) * 64 + tx * 4 + (j & 3);
            const float v = acc[i][j] + __ldg(&bias[n]);
            if (MODE == 0) {
                const int t = r >> 2;       // r / B_
                const int b = r & 3;        // r % B_
                const int h = n >> 6;       // n / 64
                const int d = n & 63;
                Y[((b * H_ + h) * T_ + t) * HD_ + d] = v;
            } else {
                Y[r * C_ + n] = v;
            }
        }
    }
}

// ---------------------------------------------------------------------------
// Flash attention, fp32. CTA = 64-query tile of one (b,h). 256 threads.
// Qs[d][q] (scaled), KP[d][k] -> reused as P[q][k], Vs[k][d].  48KB smem.
// Thread (ty,tx) owns S rows q=4ty+i / cols k=4tx+j, and O rows q=4ty+i /
// cols d=4tx+j -> softmax state (m,l,corr) lives entirely in registers;
// row reductions are 16-lane shfl_xor (same-ty threads are one warp half).
// ---------------------------------------------------------------------------
__global__ void __launch_bounds__(256) attn_kernel(
    const float* __restrict__ Q, const float* __restrict__ K,
    const float* __restrict__ V, float* __restrict__ AO)
{
    __shared__ float Qs[64][64];   // [d][q]
    __shared__ float KP[64][64];   // [d][k] during S, then [q][k] = P
    __shared__ float Vs[64][64];   // [k][d]

    const int tid = threadIdx.x;
    const int tx  = tid & 15;
    const int ty  = tid >> 4;
    const int b   = blockIdx.z;
    const int h   = blockIdx.y;
    const int q0  = blockIdx.x * 64;
    const int base = (b * H_ + h) * T_ * HD_;
    const float* Qb = Q + base;
    const float* Kb = K + base;
    const float* Vb = V + base;

    const int lrow = tid >> 2;          // 0..63
    const int lcol = (tid & 3) * 16;    // 0,16,32,48
    const float SCALE = 0.03125f;       // 1/sqrt(1024)

    // load Q tile transposed, fold in softmax scale
#pragma unroll
    for (int j = 0; j < 4; j++) {
        float4 v = *(const float4*)&Qb[(q0 + lrow) * HD_ + lcol + j * 4];
        Qs[lcol + j * 4 + 0][lrow] = v.x * SCALE;
        Qs[lcol + j * 4 + 1][lrow] = v.y * SCALE;
        Qs[lcol + j * 4 + 2][lrow] = v.z * SCALE;
        Qs[lcol + j * 4 + 3][lrow] = v.w * SCALE;
    }

    float m[4], l[4], o[4][4];
#pragma unroll
    for (int i = 0; i < 4; i++) {
        m[i] = -1e30f; l[i] = 0.f;
#pragma unroll
        for (int j = 0; j < 4; j++) o[i][j] = 0.f;
    }
    __syncthreads();

    for (int kt = 0; kt < T_ / 64; kt++) {
        const int k0 = kt * 64;
        // load K (transposed) and V (natural)
#pragma unroll
        for (int j = 0; j < 4; j++) {
            float4 kv = *(const float4*)&Kb[(k0 + lrow) * HD_ + lcol + j * 4];
            KP[lcol + j * 4 + 0][lrow] = kv.x;
            KP[lcol + j * 4 + 1][lrow] = kv.y;
            KP[lcol + j * 4 + 2][lrow] = kv.z;
            KP[lcol + j * 4 + 3][lrow] = kv.w;
            float4 vv = *(const float4*)&Vb[(k0 + lrow) * HD_ + lcol + j * 4];
            *(float4*)&Vs[lrow][lcol + j * 4] = vv;
        }
        __syncthreads();

        // S = (Q*scale) @ K^T
        float s[4][4];
#pragma unroll
        for (int i = 0; i < 4; i++)
#pragma unroll
            for (int j = 0; j < 4; j++) s[i][j] = 0.f;
#pragma unroll 8
        for (int d = 0; d < 64; d++) {
            float4 a  = *(const float4*)&Qs[d][ty * 4];
            float4 bb = *(const float4*)&KP[d][tx * 4];
            float av[4] = {a.x, a.y, a.z, a.w};
            float bv[4] = {bb.x, bb.y, bb.z, bb.w};
#pragma unroll
            for (int i = 0; i < 4; i++)
#pragma unroll
                for (int j = 0; j < 4; j++)
                    s[i][j] = fmaf(av[i], bv[j], s[i][j]);
        }
        __syncthreads();   // everyone done reading KP before it becomes P

        // online softmax (register-resident state, 16-lane row reduce)
#pragma unroll
        for (int i = 0; i < 4; i++) {
            float rmax = fmaxf(fmaxf(s[i][0], s[i][1]), fmaxf(s[i][2], s[i][3]));
#pragma unroll
            for (int off = 8; off > 0; off >>= 1)
                rmax = fmaxf(rmax, __shfl_xor_sync(0xffffffffu, rmax, off));
            const float mnew = fmaxf(m[i], rmax);
            const float corr = __expf(m[i] - mnew);
            m[i] = mnew;
            float rsum = 0.f;
#pragma unroll
            for (int j = 0; j < 4; j++) {
                s[i][j] = __expf(s[i][j] - mnew);
                rsum += s[i][j];
            }
#pragma unroll
            for (int off = 8; off > 0; off >>= 1)
                rsum += __shfl_xor_sync(0xffffffffu, rsum, off);
            l[i] = l[i] * corr + rsum;
#pragma unroll
            for (int j = 0; j < 4; j++) o[i][j] *= corr;
            *(float4*)&KP[ty * 4 + i][tx * 4] =
                make_float4(s[i][0], s[i][1], s[i][2], s[i][3]);
        }
        __syncthreads();

        // O += P @ V
#pragma unroll 8
        for (int k = 0; k < 64; k++) {
            float4 vv = *(const float4*)&Vs[k][tx * 4];
            float pv[4];
#pragma unroll
            for (int i = 0; i < 4; i++) pv[i] = KP[ty * 4 + i][k];
            float bv[4] = {vv.x, vv.y, vv.z, vv.w};
#pragma unroll
            for (int i = 0; i < 4; i++)
#pragma unroll
                for (int j = 0; j < 4; j++)
                    o[i][j] = fmaf(pv[i], bv[j], o[i][j]);
        }
        __syncthreads();   // before next tile's K/V overwrite
    }

    // epilogue: AO[b][t][h*64 + d]
#pragma unroll
    for (int i = 0; i < 4; i++) {
        const float inv = 1.f / l[i];
        const int q = q0 + ty * 4 + i;
        float4 r = make_float4(o[i][0] * inv, o[i][1] * inv,
                               o[i][2] * inv, o[i][3] * inv);
        *(float4*)&AO[(b * T_ + q) * C_ + h * HD_ + tx * 4] = r;
    }
}

// ---------------------------------------------------------------------------
extern "C" void kernel_launch(void* const* d_in, const int* in_sizes, int n_in,
                              void* d_out, int out_size)
{
    (void)in_sizes; (void)n_in; (void)out_size;
    const float* x1 = (const float*)d_in[0];
    const float* x2 = (const float*)d_in[1];
    const float* Wq = (const float*)d_in[2];
    const float* bq = (const float*)d_in[3];
    const float* Wk = (const float*)d_in[4];
    const float* bk = (const float*)d_in[5];
    const float* Wv = (const float*)d_in[6];
    const float* bv = (const float*)d_in[7];
    const float* Wu = (const float*)d_in[8];
    const float* bu = (const float*)d_in[9];
    float* out = (float*)d_out;

    float *qp, *kp, *vp, *aop;
    cudaGetSymbolAddress((void**)&qp,  g_Q);
    cudaGetSymbolAddress((void**)&kp,  g_K);
    cudaGetSymbolAddress((void**)&vp,  g_V);
    cudaGetSymbolAddress((void**)&aop, g_AO);

    dim3 gp(C_ / 128, M_ / 128);   // (8, 64)
    proj_kernel<0><<<gp, 256>>>(x1, Wq, bq, qp);
    proj_kernel<0><<<gp, 256>>>(x2, Wk, bk, kp);
    proj_kernel<0><<<gp, 256>>>(x2, Wv, bv, vp);
    attn_kernel<<<dim3(T_ / 64, H_, B_), 256>>>(qp, kp, vp, aop);
    proj_kernel<1><<<gp, 256>>>(aop, Wu, bu, out);
}

// round 6
// speedup vs baseline: 1.0006x; 1.0006x over previous
#include <cuda_runtime.h>

// ---------------------------------------------------------------------------
// MHA cross-attention, fp32 baseline.
//   q = x1 @ Wq^T + bq ; k,v = x2 @ W{k,v}^T + b ; per-head flash attention
//   (scale 1/sqrt(C)); out = concat @ Wu^T + bu, output (B,T,C).
// x layout (T,B,C): row r = t*B+b is contiguous. Q/K/V staged as [B][H][T][hd].
// ---------------------------------------------------------------------------

constexpr int T_  = 2048;
constexpr int B_  = 4;
constexpr int C_  = 1024;
constexpr int H_  = 16;
constexpr int HD_ = 64;
constexpr int M_  = T_ * B_;   // 8192 rows

// Scratch (device globals: allocation-free per harness rules). 4 x 32MB.
__device__ float g_Q[B_ * H_ * T_ * HD_];
__device__ float g_K[B_ * H_ * T_ * HD_];
__device__ float g_V[B_ * H_ * T_ * HD_];
__device__ float g_AO[B_ * T_ * C_];

// ---------------------------------------------------------------------------
// SGEMM: Y = X(MxK) @ W^T(N x K) + bias.  M=8192, N=K=1024.
// 128x128 block, BK=8, 256 threads, 8x8 per thread, double-buffered smem.
// MODE 0: scatter into QKV layout [b][h][t][d]  (r = t*B+b, n = h*64+d)
// MODE 1: plain Y[r*C + n]
// ---------------------------------------------------------------------------
template <int MODE>
__global__ void __launch_bounds__(256) proj_kernel(
    const float* __restrict__ X, const float* __restrict__ W,
    const float* __restrict__ bias, float* __restrict__ Y)
{
    __shared__ float As[2][8][128];   // [buf][k][m]
    __shared__ float Bs[2][8][128];   // [buf][k][n]

    const int tid = threadIdx.x;
    const int bm  = blockIdx.y * 128;
    const int bn  = blockIdx.x * 128;
    const int lr  = tid >> 1;          // 0..127
    const int lc  = (tid & 1) * 4;     // 0 or 4
    const int tx  = tid & 15;
    const int ty  = tid >> 4;

    const float* Xp = X + (bm + lr) * C_ + lc;
    const float* Wp = W + (bn + lr) * C_ + lc;

    float acc[8][8];
#pragma unroll
    for (int i = 0; i < 8; i++)
#pragma unroll
        for (int j = 0; j < 8; j++) acc[i][j] = 0.f;

    // preload tile 0
    {
        float4 a = *(const float4*)Xp;
        float4 b = *(const float4*)Wp;
        As[0][lc + 0][lr] = a.x; As[0][lc + 1][lr] = a.y;
        As[0][lc + 2][lr] = a.z; As[0][lc + 3][lr] = a.w;
        Bs[0][lc + 0][lr] = b.x; Bs[0][lc + 1][lr] = b.y;
        Bs[0][lc + 2][lr] = b.z; Bs[0][lc + 3][lr] = b.w;
    }
    __syncthreads();

    int buf = 0;
    const int KBLK = C_ / 8;   // 128
    for (int kt = 0; kt < KBLK; kt++) {
        float4 na, nb;
        const bool has_next = (kt + 1) < KBLK;
        if (has_next) {
            na = *(const float4*)(Xp + (kt + 1) * 8);
            nb = *(const float4*)(Wp + (kt + 1) * 8);
        }
#pragma unroll
        for (int k = 0; k < 8; k++) {
            float4 a0 = *(const float4*)&As[buf][k][ty * 4];
            float4 a1 = *(const float4*)&As[buf][k][ty * 4 + 64];
            float4 b0 = *(const float4*)&Bs[buf][k][tx * 4];
            float4 b1 = *(const float4*)&Bs[buf][k][tx * 4 + 64];
            float av[8] = {a0.x, a0.y, a0.z, a0.w, a1.x, a1.y, a1.z, a1.w};
            float bv[8] = {b0.x, b0.y, b0.z, b0.w, b1.x, b1.y, b1.z, b1.w};
#pragma unroll
            for (int i = 0; i < 8; i++)
#pragma unroll
                for (int j = 0; j < 8; j++)
                    acc[i][j] = fmaf(av[i], bv[j], acc[i][j]);
        }
        if (has_next) {
            As[buf ^ 1][lc + 0][lr] = na.x; As[buf ^ 1][lc + 1][lr] = na.y;
            As[buf ^ 1][lc + 2][lr] = na.z; As[buf ^ 1][lc + 3][lr] = na.w;
            Bs[buf ^ 1][lc + 0][lr] = nb.x; Bs[buf ^ 1][lc + 1][lr] = nb.y;
            Bs[buf ^ 1][lc + 2][lr] = nb.z; Bs[buf ^ 1][lc + 3][lr] = nb.w;
            __syncthreads();
            buf ^= 1;
        }
    }

    // epilogue
#pragma unroll
    for (int i = 0; i < 8; i++) {
        const int r = bm + (i >> 2) * 64 + ty * 4 + (i & 3);
#pragma unroll
        for (int j = 0; j < 8; j++) {
            const int n = bn + (j >> 2) * 64 + tx * 4 + (j & 3);
            const float v = acc[i][j] + __ldg(&bias[n]);
            if (MODE == 0) {
                const int t = r >> 2;       // r / B_
                const int b = r & 3;        // r % B_
                const int h = n >> 6;       // n / 64
                const int d = n & 63;
                Y[((b * H_ + h) * T_ + t) * HD_ + d] = v;
            } else {
                Y[r * C_ + n] = v;
            }
        }
    }
}

// ---------------------------------------------------------------------------
// Flash attention, fp32. CTA = 64-query tile of one (b,h). 256 threads.
// Qs[d][q] (scaled), KP[d][k] -> reused as P[q][k], Vs[k][d].  48KB smem.
// Thread (ty,tx) owns S rows q=4ty+i / cols k=4tx+j, and O rows q=4ty+i /
// cols d=4tx+j -> softmax state (m,l,corr) lives entirely in registers;
// row reductions are 16-lane shfl_xor (same-ty threads are one warp half).
// ---------------------------------------------------------------------------
__global__ void __launch_bounds__(256) attn_kernel(
    const float* __restrict__ Q, const float* __restrict__ K,
    const float* __restrict__ V, float* __restrict__ AO)
{
    __shared__ float Qs[64][64];   // [d][q]
    __shared__ float KP[64][64];   // [d][k] during S, then [q][k] = P
    __shared__ float Vs[64][64];   // [k][d]

    const int tid = threadIdx.x;
    const int tx  = tid & 15;
    const int ty  = tid >> 4;
    const int b   = blockIdx.z;
    const int h   = blockIdx.y;
    const int q0  = blockIdx.x * 64;
    const int base = (b * H_ + h) * T_ * HD_;
    const float* Qb = Q + base;
    const float* Kb = K + base;
    const float* Vb = V + base;

    const int lrow = tid >> 2;          // 0..63
    const int lcol = (tid & 3) * 16;    // 0,16,32,48
    const float SCALE = 0.03125f;       // 1/sqrt(1024)

    // load Q tile transposed, fold in softmax scale
#pragma unroll
    for (int j = 0; j < 4; j++) {
        float4 v = *(const float4*)&Qb[(q0 + lrow) * HD_ + lcol + j * 4];
        Qs[lcol + j * 4 + 0][lrow] = v.x * SCALE;
        Qs[lcol + j * 4 + 1][lrow] = v.y * SCALE;
        Qs[lcol + j * 4 + 2][lrow] = v.z * SCALE;
        Qs[lcol + j * 4 + 3][lrow] = v.w * SCALE;
    }

    float m[4], l[4], o[4][4];
#pragma unroll
    for (int i = 0; i < 4; i++) {
        m[i] = -1e30f; l[i] = 0.f;
#pragma unroll
        for (int j = 0; j < 4; j++) o[i][j] = 0.f;
    }
    __syncthreads();

    for (int kt = 0; kt < T_ / 64; kt++) {
        const int k0 = kt * 64;
        // load K (transposed) and V (natural)
#pragma unroll
        for (int j = 0; j < 4; j++) {
            float4 kv = *(const float4*)&Kb[(k0 + lrow) * HD_ + lcol + j * 4];
            KP[lcol + j * 4 + 0][lrow] = kv.x;
            KP[lcol + j * 4 + 1][lrow] = kv.y;
            KP[lcol + j * 4 + 2][lrow] = kv.z;
            KP[lcol + j * 4 + 3][lrow] = kv.w;
            float4 vv = *(const float4*)&Vb[(k0 + lrow) * HD_ + lcol + j * 4];
            *(float4*)&Vs[lrow][lcol + j * 4] = vv;
        }
        __syncthreads();

        // S = (Q*scale) @ K^T
        float s[4][4];
#pragma unroll
        for (int i = 0; i < 4; i++)
#pragma unroll
            for (int j = 0; j < 4; j++) s[i][j] = 0.f;
#pragma unroll 8
        for (int d = 0; d < 64; d++) {
            float4 a  = *(const float4*)&Qs[d][ty * 4];
            float4 bb = *(const float4*)&KP[d][tx * 4];
            float av[4] = {a.x, a.y, a.z, a.w};
            float bv[4] = {bb.x, bb.y, bb.z, bb.w};
#pragma unroll
            for (int i = 0; i < 4; i++)
#pragma unroll
                for (int j = 0; j < 4; j++)
                    s[i][j] = fmaf(av[i], bv[j], s[i][j]);
        }
        __syncthreads();   // everyone done reading KP before it becomes P

        // online softmax (register-resident state, 16-lane row reduce)
#pragma unroll
        for (int i = 0; i < 4; i++) {
            float rmax = fmaxf(fmaxf(s[i][0], s[i][1]), fmaxf(s[i][2], s[i][3]));
#pragma unroll
            for (int off = 8; off > 0; off >>= 1)
                rmax = fmaxf(rmax, __shfl_xor_sync(0xffffffffu, rmax, off));
            const float mnew = fmaxf(m[i], rmax);
            const float corr = __expf(m[i] - mnew);
            m[i] = mnew;
            float rsum = 0.f;
#pragma unroll
            for (int j = 0; j < 4; j++) {
                s[i][j] = __expf(s[i][j] - mnew);
                rsum += s[i][j];
            }
#pragma unroll
            for (int off = 8; off > 0; off >>= 1)
                rsum += __shfl_xor_sync(0xffffffffu, rsum, off);
            l[i] = l[i] * corr + rsum;
#pragma unroll
            for (int j = 0; j < 4; j++) o[i][j] *= corr;
            *(float4*)&KP[ty * 4 + i][tx * 4] =
                make_float4(s[i][0], s[i][1], s[i][2], s[i][3]);
        }
        __syncthreads();

        // O += P @ V
#pragma unroll 8
        for (int k = 0; k < 64; k++) {
            float4 vv = *(const float4*)&Vs[k][tx * 4];
            float pv[4];
#pragma unroll
            for (int i = 0; i < 4; i++) pv[i] = KP[ty * 4 + i][k];
            float bv[4] = {vv.x, vv.y, vv.z, vv.w};
#pragma unroll
            for (int i = 0; i < 4; i++)
#pragma unroll
                for (int j = 0; j < 4; j++)
                    o[i][j] = fmaf(pv[i], bv[j], o[i][j]);
        }
        __syncthreads();   // before next tile's K/V overwrite
    }

    // epilogue: AO[b][t][h*64 + d]
#pragma unroll
    for (int i = 0; i < 4; i++) {
        const float inv = 1.f / l[i];
        const int q = q0 + ty * 4 + i;
        float4 r = make_float4(o[i][0] * inv, o[i][1] * inv,
                               o[i][2] * inv, o[i][3] * inv);
        *(float4*)&AO[(b * T_ + q) * C_ + h * HD_ + tx * 4] = r;
    }
}

// ---------------------------------------------------------------------------
extern "C" void kernel_launch(void* const* d_in, const int* in_sizes, int n_in,
                              void* d_out, int out_size)
{
    (void)in_sizes; (void)n_in; (void)out_size;
    const float* x1 = (const float*)d_in[0];
    const float* x2 = (const float*)d_in[1];
    const float* Wq = (const float*)d_in[2];
    const float* bq = (const float*)d_in[3];
    const float* Wk = (const float*)d_in[4];
    const float* bk = (const float*)d_in[5];
    const float* Wv = (const float*)d_in[6];
    const float* bv = (const float*)d_in[7];
    const float* Wu = (const float*)d_in[8];
    const float* bu = (const float*)d_in[9];
    float* out = (float*)d_out;

    float *qp, *kp, *vp, *aop;
    cudaGetSymbolAddress((void**)&qp,  g_Q);
    cudaGetSymbolAddress((void**)&kp,  g_K);
    cudaGetSymbolAddress((void**)&vp,  g_V);
    cudaGetSymbolAddress((void**)&aop, g_AO);

    dim3 gp(C_ / 128, M_ / 128);   // (8, 64)
    proj_kernel<0><<<gp, 256>>>(x1, Wq, bq, qp);
    proj_kernel<0><<<gp, 256>>>(x2, Wk, bk, kp);
    proj_kernel<0><<<gp, 256>>>(x2, Wv, bv, vp);
    attn_kernel<<<dim3(T_ / 64, H_, B_), 256>>>(qp, kp, vp, aop);
    proj_kernel<1><<<gp, 256>>>(aop, Wu, bu, out);
}

// round 9
// speedup vs baseline: 1.2413x; 1.2406x over previous
#include <cuda_runtime.h>
#include <cuda_bf16.h>
#include <cstdint>

// ---------------------------------------------------------------------------
// MHA cross-attention.
//   Projections q/k/v/out: mma.sync bf16x3-split GEMM (fp32-grade accuracy).
//     (tcgen05 is unavailable: harness emits compute_103 PTX, no 'a' variant.)
//   Attention: fp32 flash kernel (at ~90% of FFMA issue roofline).
// ---------------------------------------------------------------------------

constexpr int T_  = 2048;
constexpr int B_  = 4;
constexpr int C_  = 1024;
constexpr int H_  = 16;
constexpr int HD_ = 64;
constexpr int M_  = T_ * B_;   // 8192 rows

// Scratch (device globals: allocation-free per harness rules).
__device__ float g_Q[B_ * H_ * T_ * HD_];
__device__ float g_K[B_ * H_ * T_ * HD_];
__device__ float g_V[B_ * H_ * T_ * HD_];
__device__ float g_AO[B_ * T_ * C_];

// ============================ helpers ======================================
__device__ __forceinline__ uint32_t smem_u32(const void* p) {
    uint32_t a;
    asm("{ .reg .u64 t; cvta.to.shared.u64 t, %1; cvt.u32.u64 %0, t; }"
        : "=r"(a) : "l"(p));
    return a;
}
__device__ __forceinline__ void ldsm4(uint32_t& r0, uint32_t& r1,
                                      uint32_t& r2, uint32_t& r3, uint32_t a) {
    asm volatile("ldmatrix.sync.aligned.m8n8.x4.shared.b16 {%0,%1,%2,%3}, [%4];"
                 : "=r"(r0), "=r"(r1), "=r"(r2), "=r"(r3) : "r"(a));
}
__device__ __forceinline__ void mma_bf16(float* c, const uint32_t* a,
                                         const uint32_t* b) {
    asm volatile(
        "mma.sync.aligned.m16n8k16.row.col.f32.bf16.bf16.f32 "
        "{%0,%1,%2,%3}, {%4,%5,%6,%7}, {%8,%9}, {%0,%1,%2,%3};"
        : "+f"(c[0]), "+f"(c[1]), "+f"(c[2]), "+f"(c[3])
        : "r"(a[0]), "r"(a[1]), "r"(a[2]), "r"(a[3]), "r"(b[0]), "r"(b[1]));
}

// fp32x4 -> (hi bf16x4, lo bf16x4) packed as uint2 each
__device__ __forceinline__ void split4(float4 v, uint2& h, uint2& l) {
    __nv_bfloat16 hx = __float2bfloat16_rn(v.x), hy = __float2bfloat16_rn(v.y);
    __nv_bfloat16 hz = __float2bfloat16_rn(v.z), hw = __float2bfloat16_rn(v.w);
    __nv_bfloat16 lx = __float2bfloat16_rn(v.x - __bfloat162float(hx));
    __nv_bfloat16 ly = __float2bfloat16_rn(v.y - __bfloat162float(hy));
    __nv_bfloat16 lz = __float2bfloat16_rn(v.z - __bfloat162float(hz));
    __nv_bfloat16 lw = __float2bfloat16_rn(v.w - __bfloat162float(hw));
    h.x = (uint32_t)__bfloat16_as_ushort(hx) | ((uint32_t)__bfloat16_as_ushort(hy) << 16);
    h.y = (uint32_t)__bfloat16_as_ushort(hz) | ((uint32_t)__bfloat16_as_ushort(hw) << 16);
    l.x = (uint32_t)__bfloat16_as_ushort(lx) | ((uint32_t)__bfloat16_as_ushort(ly) << 16);
    l.y = (uint32_t)__bfloat16_as_ushort(lz) | ((uint32_t)__bfloat16_as_ushort(lw) << 16);
}

// ============================ projection ===================================
// Y = X(MxK) @ W^T(NxK) + bias,  bf16x3 split on mma.sync.
// Block tile 128x128, K-chunk 32 fp32. 8 warps, warp tile 64x32.
// smem buffer = {Ahi,Alo,Bhi,Blo} 128x32 bf16 tiles, 64B rows, XOR swizzle:
//   off(row,col8chunk ch) = row*64 + ((ch ^ ((row>>1)&3))<<4)     (conflict-free
//   per ldmatrix 8-address phase and for the split 8B stores).
constexpr int PROJ_BUF  = 4 * 128 * 32 * 2;   // 32768 B
constexpr int PROJ_SMEM = 2 * PROJ_BUF;       // 65536 B (double buffered)

// MODE 0: scatter to [b][h][t][d] (r = t*B+b, n = h*64+d); MODE 1: Y[r*C+n].
template <int MODE>
__global__ void __launch_bounds__(256, 1) proj_mma(
    const float* __restrict__ X, const float* __restrict__ W,
    const float* __restrict__ bias, float* __restrict__ Y)
{
    extern __shared__ char smem[];
    const uint32_t sbase = smem_u32(smem);
    const int tid = threadIdx.x;
    const int wid = tid >> 5;
    const int lid = tid & 31;
    const int bm  = blockIdx.y * 128;
    const int bn  = blockIdx.x * 128;

    const int wm = wid & 1;        // 2 m-tiles of 64
    const int wn = wid >> 1;       // 4 n-tiles of 32

    // ldmatrix lane geometry
    const int rA = lid & 15;                       // A: row within 16
    const int cA = lid >> 4;                       // A: chunk offset (k-half)
    const int rB = ((lid >> 4) << 3) + (lid & 7);  // B: row within 16 (n)
    const int cB = (lid >> 3) & 1;                 // B: chunk offset (k-half)

    // global staging geometry (per thread, 4 segments)
    int grow[4], gc4[4];
#pragma unroll
    for (int i = 0; i < 4; i++) {
        const int f = tid + i * 256;   // 0..1023
        grow[i] = f >> 3;              // 0..127
        gc4[i]  = f & 7;               // float4 col index
    }

    float acc[4][4][4];
#pragma unroll
    for (int mf = 0; mf < 4; mf++)
#pragma unroll
        for (int nf = 0; nf < 4; nf++)
#pragma unroll
            for (int j = 0; j < 4; j++) acc[mf][nf][j] = 0.f;

    float4 ga[4], gb[4];

    auto load_regs = [&](int kt) {
#pragma unroll
        for (int i = 0; i < 4; i++) {
            ga[i] = *(const float4*)(X + (size_t)(bm + grow[i]) * C_ + kt * 32 + gc4[i] * 4);
            gb[i] = *(const float4*)(W + (size_t)(bn + grow[i]) * C_ + kt * 32 + gc4[i] * 4);
        }
    };
    auto store_split = [&](char* buf) {
#pragma unroll
        for (int i = 0; i < 4; i++) {
            const int row = grow[i], c4 = gc4[i];
            const uint32_t o = row * 64 +
                ((((c4 >> 1) ^ ((row >> 1) & 3))) << 4) + (c4 & 1) * 8;
            uint2 h, l;
            split4(ga[i], h, l);
            *(uint2*)(buf + o)         = h;   // Ahi
            *(uint2*)(buf + 8192 + o)  = l;   // Alo
            split4(gb[i], h, l);
            *(uint2*)(buf + 16384 + o) = h;   // Bhi
            *(uint2*)(buf + 24576 + o) = l;   // Blo
        }
    };
    auto compute = [&](uint32_t bb) {
        const uint32_t ahi = bb, alo = bb + 8192, bhi = bb + 16384, blo = bb + 24576;
#pragma unroll
        for (int ks = 0; ks < 2; ks++) {
            uint32_t bh[4][2], bl[4][2];
#pragma unroll
            for (int p = 0; p < 2; p++) {
                const int rowB = wn * 32 + p * 16 + rB;
                const uint32_t off = rowB * 64 +
                    (((ks * 2 + cB) ^ ((rowB >> 1) & 3)) << 4);
                ldsm4(bh[2*p][0], bh[2*p][1], bh[2*p+1][0], bh[2*p+1][1], bhi + off);
                ldsm4(bl[2*p][0], bl[2*p][1], bl[2*p+1][0], bl[2*p+1][1], blo + off);
            }
#pragma unroll
            for (int mf = 0; mf < 4; mf++) {
                const int rowA = wm * 64 + mf * 16 + rA;
                const uint32_t off = rowA * 64 +
                    (((ks * 2 + cA) ^ ((rowA >> 1) & 3)) << 4);
                uint32_t ah[4], al[4];
                ldsm4(ah[0], ah[1], ah[2], ah[3], ahi + off);
                ldsm4(al[0], al[1], al[2], al[3], alo + off);
#pragma unroll
                for (int nf = 0; nf < 4; nf++) {
                    mma_bf16(acc[mf][nf], ah, bh[nf]);
                    mma_bf16(acc[mf][nf], ah, bl[nf]);
                    mma_bf16(acc[mf][nf], al, bh[nf]);
                }
            }
        }
    };

    // pipeline: double-buffered smem, register-staged global prefetch
    load_regs(0);
    store_split(smem);
    __syncthreads();
    int cur = 0;
    const int NCHUNK = C_ / 32;   // 32
    for (int kt = 0; kt < NCHUNK; kt++) {
        const bool has_next = (kt + 1) < NCHUNK;
        if (has_next) load_regs(kt + 1);
        compute(sbase + cur * PROJ_BUF);
        if (has_next) {
            store_split(smem + (cur ^ 1) * PROJ_BUF);
            __syncthreads();
            cur ^= 1;
        }
    }

    // epilogue: frag (mf,nf): rows m, m+8 ; cols n0, n0+1
#pragma unroll
    for (int mf = 0; mf < 4; mf++) {
        const int m = bm + wm * 64 + mf * 16 + (lid >> 2);
#pragma unroll
        for (int nf = 0; nf < 4; nf++) {
            const int n0 = bn + wn * 32 + nf * 8 + (lid & 3) * 2;
            const float2 bb = *(const float2*)(bias + n0);
            float2 v0 = make_float2(acc[mf][nf][0] + bb.x, acc[mf][nf][1] + bb.y);
            float2 v1 = make_float2(acc[mf][nf][2] + bb.x, acc[mf][nf][3] + bb.y);
            if (MODE == 0) {
                const int h = n0 >> 6, d = n0 & 63;
                int t = m >> 2, b2 = m & 3;
                *(float2*)&Y[((b2 * H_ + h) * T_ + t) * HD_ + d] = v0;
                t = (m + 8) >> 2; b2 = (m + 8) & 3;
                *(float2*)&Y[((b2 * H_ + h) * T_ + t) * HD_ + d] = v1;
            } else {
                *(float2*)&Y[(size_t)m * C_ + n0]       = v0;
                *(float2*)&Y[(size_t)(m + 8) * C_ + n0] = v1;
            }
        }
    }
}

// ---------------------------------------------------------------------------
// Flash attention, fp32 (unchanged — at ~90% of FFMA issue roofline).
// ---------------------------------------------------------------------------
__global__ void __launch_bounds__(256) attn_kernel(
    const float* __restrict__ Q, const float* __restrict__ K,
    const float* __restrict__ V, float* __restrict__ AO)
{
    __shared__ float Qs[64][64];   // [d][q]
    __shared__ float KP[64][64];   // [d][k] during S, then [q][k] = P
    __shared__ float Vs[64][64];   // [k][d]

    const int tid = threadIdx.x;
    const int tx  = tid & 15;
    const int ty  = tid >> 4;
    const int b   = blockIdx.z;
    const int h   = blockIdx.y;
    const int q0  = blockIdx.x * 64;
    const int base = (b * H_ + h) * T_ * HD_;
    const float* Qb = Q + base;
    const float* Kb = K + base;
    const float* Vb = V + base;

    const int lrow = tid >> 2;
    const int lcol = (tid & 3) * 16;
    const float SCALE = 0.03125f;   // 1/sqrt(1024)

#pragma unroll
    for (int j = 0; j < 4; j++) {
        float4 v = *(const float4*)&Qb[(q0 + lrow) * HD_ + lcol + j * 4];
        Qs[lcol + j * 4 + 0][lrow] = v.x * SCALE;
        Qs[lcol + j * 4 + 1][lrow] = v.y * SCALE;
        Qs[lcol + j * 4 + 2][lrow] = v.z * SCALE;
        Qs[lcol + j * 4 + 3][lrow] = v.w * SCALE;
    }

    float m[4], l[4], o[4][4];
#pragma unroll
    for (int i = 0; i < 4; i++) {
        m[i] = -1e30f; l[i] = 0.f;
#pragma unroll
        for (int j = 0; j < 4; j++) o[i][j] = 0.f;
    }
    __syncthreads();

    for (int kt = 0; kt < T_ / 64; kt++) {
        const int k0 = kt * 64;
#pragma unroll
        for (int j = 0; j < 4; j++) {
            float4 kv = *(const float4*)&Kb[(k0 + lrow) * HD_ + lcol + j * 4];
            KP[lcol + j * 4 + 0][lrow] = kv.x;
            KP[lcol + j * 4 + 1][lrow] = kv.y;
            KP[lcol + j * 4 + 2][lrow] = kv.z;
            KP[lcol + j * 4 + 3][lrow] = kv.w;
            float4 vv = *(const float4*)&Vb[(k0 + lrow) * HD_ + lcol + j * 4];
            *(float4*)&Vs[lrow][lcol + j * 4] = vv;
        }
        __syncthreads();

        float s[4][4];
#pragma unroll
        for (int i = 0; i < 4; i++)
#pragma unroll
            for (int j = 0; j < 4; j++) s[i][j] = 0.f;
#pragma unroll 8
        for (int d = 0; d < 64; d++) {
            float4 a  = *(const float4*)&Qs[d][ty * 4];
            float4 bb = *(const float4*)&KP[d][tx * 4];
            float av[4] = {a.x, a.y, a.z, a.w};
            float bv[4] = {bb.x, bb.y, bb.z, bb.w};
#pragma unroll
            for (int i = 0; i < 4; i++)
#pragma unroll
                for (int j = 0; j < 4; j++)
                    s[i][j] = fmaf(av[i], bv[j], s[i][j]);
        }
        __syncthreads();

#pragma unroll
        for (int i = 0; i < 4; i++) {
            float rmax = fmaxf(fmaxf(s[i][0], s[i][1]), fmaxf(s[i][2], s[i][3]));
#pragma unroll
            for (int off = 8; off > 0; off >>= 1)
                rmax = fmaxf(rmax, __shfl_xor_sync(0xffffffffu, rmax, off));
            const float mnew = fmaxf(m[i], rmax);
            const float corr = __expf(m[i] - mnew);
            m[i] = mnew;
            float rsum = 0.f;
#pragma unroll
            for (int j = 0; j < 4; j++) {
                s[i][j] = __expf(s[i][j] - mnew);
                rsum += s[i][j];
            }
#pragma unroll
            for (int off = 8; off > 0; off >>= 1)
                rsum += __shfl_xor_sync(0xffffffffu, rsum, off);
            l[i] = l[i] * corr + rsum;
#pragma unroll
            for (int j = 0; j < 4; j++) o[i][j] *= corr;
            *(float4*)&KP[ty * 4 + i][tx * 4] =
                make_float4(s[i][0], s[i][1], s[i][2], s[i][3]);
        }
        __syncthreads();

#pragma unroll 8
        for (int k = 0; k < 64; k++) {
            float4 vv = *(const float4*)&Vs[k][tx * 4];
            float pv[4];
#pragma unroll
            for (int i = 0; i < 4; i++) pv[i] = KP[ty * 4 + i][k];
            float bv[4] = {vv.x, vv.y, vv.z, vv.w};
#pragma unroll
            for (int i = 0; i < 4; i++)
#pragma unroll
                for (int j = 0; j < 4; j++)
                    o[i][j] = fmaf(pv[i], bv[j], o[i][j]);
        }
        __syncthreads();
    }

#pragma unroll
    for (int i = 0; i < 4; i++) {
        const float inv = 1.f / l[i];
        const int q = q0 + ty * 4 + i;
        float4 r = make_float4(o[i][0] * inv, o[i][1] * inv,
                               o[i][2] * inv, o[i][3] * inv);
        *(float4*)&AO[(b * T_ + q) * C_ + h * HD_ + tx * 4] = r;
    }
}

// ---------------------------------------------------------------------------
extern "C" void kernel_launch(void* const* d_in, const int* in_sizes, int n_in,
                              void* d_out, int out_size)
{
    (void)in_sizes; (void)n_in; (void)out_size;
    const float* x1 = (const float*)d_in[0];
    const float* x2 = (const float*)d_in[1];
    const float* Wq = (const float*)d_in[2];
    const float* bq = (const float*)d_in[3];
    const float* Wk = (const float*)d_in[4];
    const float* bk = (const float*)d_in[5];
    const float* Wv = (const float*)d_in[6];
    const float* bv = (const float*)d_in[7];
    const float* Wu = (const float*)d_in[8];
    const float* bu = (const float*)d_in[9];
    float* out = (float*)d_out;

    float *qp, *kp, *vp, *aop;
    cudaGetSymbolAddress((void**)&qp,  g_Q);
    cudaGetSymbolAddress((void**)&kp,  g_K);
    cudaGetSymbolAddress((void**)&vp,  g_V);
    cudaGetSymbolAddress((void**)&aop, g_AO);

    cudaFuncSetAttribute(proj_mma<0>, cudaFuncAttributeMaxDynamicSharedMemorySize, PROJ_SMEM);
    cudaFuncSetAttribute(proj_mma<1>, cudaFuncAttributeMaxDynamicSharedMemorySize, PROJ_SMEM);

    dim3 gp(C_ / 128, M_ / 128);   // (8, 64)
    proj_mma<0><<<gp, 256, PROJ_SMEM>>>(x1, Wq, bq, qp);
    proj_mma<0><<<gp, 256, PROJ_SMEM>>>(x2, Wk, bk, kp);
    proj_mma<0><<<gp, 256, PROJ_SMEM>>>(x2, Wv, bv, vp);
    attn_kernel<<<dim3(T_ / 64, H_, B_), 256>>>(qp, kp, vp, aop);
    proj_mma<1><<<gp, 256, PROJ_SMEM>>>(aop, Wu, bu, out);
}